// round 10
// baseline (speedup 1.0000x reference)
#include <cuda_runtime.h>
#include <cuda_bf16.h>
#include <cstdint>
#include <math.h>

#define BATCH 8
#define LSEQ  2048
#define HD    1024
#define PD    512
#define M     (BATCH*LSEQ)   // 16384
#define NN    1024           // 2*P
#define KK    1024
#define CH    32
#define LC    64

// ---------------- scratch ---------------------------------------------------
__device__ float          g_X  [(size_t)M*NN];    // Bu fp32
__device__ __nv_bfloat16  g_Ah [(size_t)M*KK];    // signal hi
__device__ __nv_bfloat16  g_Al [(size_t)M*KK];    // signal lo
__device__ __nv_bfloat16  g_Xh [(size_t)M*NN];    // xs hi
__device__ __nv_bfloat16  g_Xl [(size_t)M*NN];    // xs lo
__device__ __nv_bfloat16  g_W1h[(size_t)NN*KK];   // [n=np][k=h]
__device__ __nv_bfloat16  g_W1l[(size_t)NN*KK];
__device__ __nv_bfloat16  g_W2h[(size_t)NN*KK];   // [n=h_out][k=np]
__device__ __nv_bfloat16  g_W2l[(size_t)NN*KK];
__device__ float2 g_lam[PD];
__device__ float2 g_lam64[PD];
__device__ float2 g_f[PD];
__device__ float2 g_carry[BATCH*CH*PD];
__device__ float2 g_cin  [BATCH*CH*PD];

// ---------------- helpers ----------------------------------------------------
__device__ __forceinline__ uint32_t smem_u32(const void* p) {
    uint32_t a;
    asm("{ .reg .u64 t; cvta.to.shared.u64 t, %1; cvt.u32.u64 %0, t; }" : "=r"(a) : "l"(p));
    return a;
}
__device__ __forceinline__ void cpa16(uint32_t dst, const void* src) {
    asm volatile("cp.async.cg.shared.global [%0], [%1], 16;" :: "r"(dst), "l"(src));
}
#define CP_COMMIT() asm volatile("cp.async.commit_group;" ::: "memory")
#define LDSM_X4(r0,r1,r2,r3,addr) \
    asm volatile("ldmatrix.sync.aligned.m8n8.x4.shared.b16 {%0,%1,%2,%3}, [%4];" \
        : "=r"(r0), "=r"(r1), "=r"(r2), "=r"(r3) : "r"(addr))
#define MMA16816(d, a, b0, b1) \
    asm volatile("mma.sync.aligned.m16n8k16.row.col.f32.bf16.bf16.f32 " \
        "{%0,%1,%2,%3}, {%4,%5,%6,%7}, {%8,%9}, {%0,%1,%2,%3};" \
        : "+f"((d)[0]), "+f"((d)[1]), "+f"((d)[2]), "+f"((d)[3]) \
        : "r"((a)[0]), "r"((a)[1]), "r"((a)[2]), "r"((a)[3]), "r"(b0), "r"(b1))

__device__ __forceinline__ void split_bf16(float v, __nv_bfloat16& h, __nv_bfloat16& l) {
    h = __float2bfloat16_rn(v);
    l = __float2bfloat16_rn(v - __bfloat162float(h));
}

// ---------------- stage 0a ---------------------------------------------------
__global__ void prep_lam_kernel(const float* __restrict__ Lre,
                                const float* __restrict__ Lim,
                                const float* __restrict__ log_step)
{
    int p = threadIdx.x;
    if (p >= PD) return;
    float lr = Lre[p], li = Lim[p];
    float step = (float)exp((double)log_step[p]);
    double theta = (double)(li * step);
    double a     = (double)(lr * step);
    double s, c;
    sincos(theta, &s, &c);
    double mag = exp(a);
    float lbr = (float)(mag * c);
    float lbi = (float)(mag * s);
    g_lam[p] = make_float2(lbr, lbi);
    double s64, c64;
    sincos(64.0 * theta, &s64, &c64);
    double mag64 = exp(64.0 * a);
    g_lam64[p] = make_float2((float)(mag64 * c64), (float)(mag64 * s64));
    float ar = lbr - 1.0f, ai = lbi;
    float den = lr*lr + li*li;
    g_f[p] = make_float2((ar*lr + ai*li) / den, (ai*lr - ar*li) / den);
}

// ---------------- stage 0b ---------------------------------------------------
__global__ void prep_w_kernel(const float* __restrict__ Bv,   // (P,H,2)
                              const float* __restrict__ Cv)   // (H,P,2)
{
    int t = blockIdx.x * blockDim.x + threadIdx.x;
    {
        int n = t >> 10, h = t & 1023;
        int p = n >> 1, c = n & 1;
        float2 f = g_f[p];
        float br = Bv[((size_t)p*HD + h)*2 + 0];
        float bi = Bv[((size_t)p*HD + h)*2 + 1];
        float w = (c == 0) ? (f.x*br - f.y*bi) : (f.x*bi + f.y*br);
        split_bf16(w, g_W1h[t], g_W1l[t]);
    }
    {
        // t = h*1024 + 2p + c  ->  g_W2h[h][np=2p+c]
        float w = Cv[t] * ((t & 1) ? -2.0f : 2.0f);
        split_bf16(w, g_W2h[t], g_W2l[t]);
    }
}

__global__ void conv_sig_kernel(const float* __restrict__ sig)
{
    size_t t = (size_t)blockIdx.x * blockDim.x + threadIdx.x;
    float4 v = *(const float4*)(sig + t*4);
    __nv_bfloat16 h0,h1,h2,h3,l0,l1,l2,l3;
    split_bf16(v.x, h0, l0); split_bf16(v.y, h1, l1);
    split_bf16(v.z, h2, l2); split_bf16(v.w, h3, l3);
    ((__nv_bfloat162*)g_Ah)[t*2+0] = __nv_bfloat162(h0, h1);
    ((__nv_bfloat162*)g_Ah)[t*2+1] = __nv_bfloat162(h2, h3);
    ((__nv_bfloat162*)g_Al)[t*2+0] = __nv_bfloat162(l0, l1);
    ((__nv_bfloat162*)g_Al)[t*2+1] = __nv_bfloat162(l2, l3);
}

// ---------------- HMMA GEMM: 512 threads, 4-stage pipeline -------------------
#define AS_STRIDE 40
#define TILE_SM   (128*AS_STRIDE*2)    // 10240 B
#define BUF_SM    (4*TILE_SM)          // 40960 B per stage
#define NSTAGE    4
#define GEMM_SMEM (NSTAGE*BUF_SM)      // 163840 B

template<bool SECOND>
__global__ __launch_bounds__(512, 1)
void gemm_hmma(float* __restrict__ Cout, const float* __restrict__ sig,
               const float* __restrict__ Dv)
{
    extern __shared__ __align__(16) char smem[];
    const uint32_t sb = smem_u32(smem);
    const int tid = threadIdx.x;
    const int wid = tid >> 5, lane = tid & 31;
    const int wm = wid & 3, wn = wid >> 2;           // 4 x 4 warp grid, 32x32 tiles
    const int bm = blockIdx.y * 128, bn = blockIdx.x * 128;

    const __nv_bfloat16* srcs[4];
    if (SECOND) { srcs[0] = g_Xh; srcs[1] = g_Xl; srcs[2] = g_W2h; srcs[3] = g_W2l; }
    else        { srcs[0] = g_Ah; srcs[1] = g_Al; srcs[2] = g_W1h; srcs[3] = g_W1l; }

    // per-thread load slot: one 16B chunk per tile (512 threads = 128 rows x 4)
    const int ldrow = tid >> 2;
    const int ldc   = tid & 3;

    auto issue = [&](int buf, int k0) {
        #pragma unroll
        for (int t4 = 0; t4 < 4; t4++) {
            const __nv_bfloat16* src = srcs[t4];
            const int rowbase = (t4 < 2) ? bm : bn;
            const void* g = src + (size_t)(rowbase + ldrow) * 1024 + k0 + ldc * 8;
            uint32_t d = sb + buf*BUF_SM + t4*TILE_SM + ldrow*(AS_STRIDE*2) + ldc*16;
            cpa16(d, g);
        }
        CP_COMMIT();
    };

    float acc[2][4][4];
    #pragma unroll
    for (int i = 0; i < 2; i++)
        #pragma unroll
        for (int j = 0; j < 4; j++)
            #pragma unroll
            for (int q = 0; q < 4; q++) acc[i][j][q] = 0.0f;

    const int a_row = wm*32 + (lane & 15);
    const int a_kc8 = (lane >> 4) << 3;
    const int b_row = wn*32 + ((lane >> 4) << 3) + (lane & 7);
    const int b_kc8 = ((lane >> 3) & 1) << 3;

    issue(0, 0);
    issue(1, 32);
    issue(2, 64);

    for (int k = 0; k < 32; k++) {
        // drain so that group k is complete
        if (k < 30)      asm volatile("cp.async.wait_group 2;" ::: "memory");
        else if (k == 30) asm volatile("cp.async.wait_group 1;" ::: "memory");
        else              asm volatile("cp.async.wait_group 0;" ::: "memory");
        __syncthreads();

        if (k < 29) issue((k + 3) & (NSTAGE - 1), (k + 3) * 32);

        const uint32_t base = sb + (k & (NSTAGE - 1)) * BUF_SM;
        #pragma unroll
        for (int ks = 0; ks < 2; ks++) {
            const int k16 = ks * 16;
            uint32_t ah[2][4], al[2][4], b[2][4];
            #pragma unroll
            for (int mf = 0; mf < 2; mf++) {
                uint32_t ao = base + (uint32_t)((a_row + mf*16)*(AS_STRIDE*2) + (k16 + a_kc8)*2);
                LDSM_X4(ah[mf][0], ah[mf][1], ah[mf][2], ah[mf][3], ao);
                LDSM_X4(al[mf][0], al[mf][1], al[mf][2], al[mf][3], ao + TILE_SM);
            }
            // Bh pass: Ah*Bh + Al*Bh
            #pragma unroll
            for (int nf2 = 0; nf2 < 2; nf2++) {
                uint32_t bo = base + 2*TILE_SM +
                    (uint32_t)((b_row + nf2*16)*(AS_STRIDE*2) + (k16 + b_kc8)*2);
                LDSM_X4(b[nf2][0], b[nf2][1], b[nf2][2], b[nf2][3], bo);
            }
            #pragma unroll
            for (int mf = 0; mf < 2; mf++)
                #pragma unroll
                for (int nf = 0; nf < 4; nf++) {
                    const int n2 = nf >> 1, hh = (nf & 1) << 1;
                    MMA16816(acc[mf][nf], ah[mf], b[n2][hh], b[n2][hh+1]);
                    MMA16816(acc[mf][nf], al[mf], b[n2][hh], b[n2][hh+1]);
                }
            // Bl pass: Ah*Bl
            #pragma unroll
            for (int nf2 = 0; nf2 < 2; nf2++) {
                uint32_t bo = base + 3*TILE_SM +
                    (uint32_t)((b_row + nf2*16)*(AS_STRIDE*2) + (k16 + b_kc8)*2);
                LDSM_X4(b[nf2][0], b[nf2][1], b[nf2][2], b[nf2][3], bo);
            }
            #pragma unroll
            for (int mf = 0; mf < 2; mf++)
                #pragma unroll
                for (int nf = 0; nf < 4; nf++) {
                    const int n2 = nf >> 1, hh = (nf & 1) << 1;
                    MMA16816(acc[mf][nf], ah[mf], b[n2][hh], b[n2][hh+1]);
                }
        }
    }

    // ---- epilogue ----
    const int r0 = lane >> 2;
    const int c0 = (lane & 3) * 2;
    #pragma unroll
    for (int mf = 0; mf < 2; mf++) {
        #pragma unroll
        for (int nf = 0; nf < 4; nf++) {
            int row = bm + wm*32 + mf*16 + r0;
            int col = bn + wn*32 + nf*8 + c0;
            float2 v0 = make_float2(acc[mf][nf][0], acc[mf][nf][1]);
            float2 v1 = make_float2(acc[mf][nf][2], acc[mf][nf][3]);
            size_t o0 = (size_t)row * 1024 + col;
            size_t o1 = (size_t)(row + 8) * 1024 + col;
            if (SECOND) {
                float2 s0 = *(const float2*)(sig + o0);
                float2 s1 = *(const float2*)(sig + o1);
                float2 d2 = *(const float2*)(Dv + col);
                v0.x = fmaf(d2.x, s0.x, v0.x); v0.y = fmaf(d2.y, s0.y, v0.y);
                v1.x = fmaf(d2.x, s1.x, v1.x); v1.y = fmaf(d2.y, s1.y, v1.y);
            }
            float* out = SECOND ? Cout : g_X;
            *(float2*)(out + o0) = v0;
            *(float2*)(out + o1) = v1;
        }
    }
}

// ---------------- chunked scan -----------------------------------------------
__global__ void scanA_kernel()
{
    int id = blockIdx.x * blockDim.x + threadIdx.x;
    int p = id & (PD - 1);
    int bc = id >> 9;
    int c = bc & (CH - 1);
    int b = bc >> 5;
    float2 lam = g_lam[p];
    const float2* base = (const float2*)(g_X + (size_t)(b*LSEQ + c*LC) * NN) + p;
    float xr = 0.0f, xi = 0.0f;
    #pragma unroll 4
    for (int j = 0; j < LC; j++) {
        float2 bu = base[(size_t)j * (NN/2)];
        float nr = fmaf(lam.x, xr, fmaf(-lam.y, xi, bu.x));
        float ni = fmaf(lam.x, xi, fmaf( lam.y, xr, bu.y));
        xr = nr; xi = ni;
    }
    g_carry[id] = make_float2(xr, xi);
}

__global__ void scanB_kernel()
{
    int id = blockIdx.x * blockDim.x + threadIdx.x;
    if (id >= BATCH * PD) return;
    int b = id >> 9, p = id & (PD - 1);
    float2 l64 = g_lam64[p];
    float2 cur = make_float2(0.0f, 0.0f);
    for (int c = 0; c < CH; c++) {
        int idx = (b*CH + c)*PD + p;
        g_cin[idx] = cur;
        float2 bc = g_carry[idx];
        float nr = fmaf(l64.x, cur.x, fmaf(-l64.y, cur.y, bc.x));
        float ni = fmaf(l64.x, cur.y, fmaf( l64.y, cur.x, bc.y));
        cur = make_float2(nr, ni);
    }
}

__global__ void scanC_kernel(float* __restrict__ state_out, int mode)
{
    int id = blockIdx.x * blockDim.x + threadIdx.x;
    int p = id & (PD - 1);
    int bc = id >> 9;
    int c = bc & (CH - 1);
    int b = bc >> 5;
    float2 lam = g_lam[p];
    float2 x = g_cin[id];
    size_t row0 = (size_t)(b*LSEQ + c*LC);
    const float2* base = (const float2*)(g_X + row0 * NN) + p;
    __nv_bfloat162* oh = (__nv_bfloat162*)g_Xh + row0 * (NN/2) + p;
    __nv_bfloat162* ol = (__nv_bfloat162*)g_Xl + row0 * (NN/2) + p;
    #pragma unroll 4
    for (int j = 0; j < LC; j++) {
        float2 bu = base[(size_t)j * (NN/2)];
        float nr = fmaf(lam.x, x.x, fmaf(-lam.y, x.y, bu.x));
        float ni = fmaf(lam.x, x.y, fmaf( lam.y, x.x, bu.y));
        x = make_float2(nr, ni);
        __nv_bfloat16 hr, lr_, hi_, li_;
        split_bf16(x.x, hr, lr_);
        split_bf16(x.y, hi_, li_);
        oh[(size_t)j * (NN/2)] = __nv_bfloat162(hr, hi_);
        ol[(size_t)j * (NN/2)] = __nv_bfloat162(lr_, li_);
    }
    if (c == CH - 1) {
        int sid = b * PD + p;
        if (mode == 2)       ((float2*)state_out)[sid] = x;
        else if (mode == 1)  state_out[sid] = x.x;
    }
}

// ---------------- launch -----------------------------------------------------
extern "C" void kernel_launch(void* const* d_in, const int* in_sizes, int n_in,
                              void* d_out, int out_size)
{
    const float* signal = (const float*)d_in[0];
    const float* Lre    = (const float*)d_in[2];
    const float* Lim    = (const float*)d_in[3];
    const float* Bv     = (const float*)d_in[4];
    const float* Cv     = (const float*)d_in[5];
    const float* Dv     = (const float*)d_in[6];
    const float* lstep  = (const float*)d_in[7];
    (void)in_sizes; (void)n_in;

    float* y = (float*)d_out;
    long rem = (long)out_size - (long)M * HD;
    int mode = (rem >= 2L*BATCH*PD) ? 2 : (rem >= (long)BATCH*PD ? 1 : 0);
    float* state_out = y + (size_t)M * HD;

    cudaFuncSetAttribute(gemm_hmma<false>, cudaFuncAttributeMaxDynamicSharedMemorySize, GEMM_SMEM);
    cudaFuncSetAttribute(gemm_hmma<true>,  cudaFuncAttributeMaxDynamicSharedMemorySize, GEMM_SMEM);

    prep_lam_kernel<<<1, PD>>>(Lre, Lim, lstep);
    prep_w_kernel<<<(NN*KK)/256, 256>>>(Bv, Cv);
    conv_sig_kernel<<<((size_t)M*KK/4)/256, 256>>>(signal);

    dim3 grid(NN/128, M/128);   // (8, 128)
    gemm_hmma<false><<<grid, 512, GEMM_SMEM>>>(nullptr, nullptr, nullptr);

    scanA_kernel<<<(BATCH*CH*PD)/256, 256>>>();
    scanB_kernel<<<(BATCH*PD)/256, 256>>>();
    scanC_kernel<<<(BATCH*CH*PD)/256, 256>>>(state_out, mode);

    gemm_hmma<true><<<grid, 512, GEMM_SMEM>>>(y, signal, Dv);
}

// round 11
// speedup vs baseline: 1.2965x; 1.2965x over previous
#include <cuda_runtime.h>
#include <cuda_bf16.h>
#include <cuda_fp16.h>
#include <cstdint>
#include <math.h>

#define BATCH 8
#define LSEQ  2048
#define HD    1024
#define PD    512
#define M     (BATCH*LSEQ)   // 16384
#define NN    1024           // 2*P
#define KK    1024
#define CH    32
#define LC    64
#define W1SC  1024.0f        // W1 pre-scale (exact power of 2)
#define INVSC (1.0f/1024.0f)

// ---------------- scratch ---------------------------------------------------
__device__ float   g_X  [(size_t)M*NN];    // 1024*Bu fp32 (GEMM1 out, scan in)
__device__ __half  g_Af [(size_t)M*KK];    // signal fp16
__device__ __half  g_Xf [(size_t)M*NN];    // xs fp16
__device__ __half  g_W1h[(size_t)NN*KK];   // [np][h], scaled by 1024
__device__ __half  g_W1l[(size_t)NN*KK];
__device__ __half  g_W2h[(size_t)NN*KK];   // [h][np]
__device__ __half  g_W2l[(size_t)NN*KK];
__device__ float2 g_lam[PD];
__device__ float2 g_lam64[PD];
__device__ float2 g_f[PD];
__device__ float2 g_carry[BATCH*CH*PD];
__device__ float2 g_cin  [BATCH*CH*PD];

// ---------------- helpers ----------------------------------------------------
__device__ __forceinline__ uint32_t smem_u32(const void* p) {
    uint32_t a;
    asm("{ .reg .u64 t; cvta.to.shared.u64 t, %1; cvt.u32.u64 %0, t; }" : "=r"(a) : "l"(p));
    return a;
}
__device__ __forceinline__ void cpa16(uint32_t dst, const void* src) {
    asm volatile("cp.async.cg.shared.global [%0], [%1], 16;" :: "r"(dst), "l"(src));
}
#define CP_COMMIT() asm volatile("cp.async.commit_group;" ::: "memory")
#define LDSM_X4(r0,r1,r2,r3,addr) \
    asm volatile("ldmatrix.sync.aligned.m8n8.x4.shared.b16 {%0,%1,%2,%3}, [%4];" \
        : "=r"(r0), "=r"(r1), "=r"(r2), "=r"(r3) : "r"(addr))
#define MMA16816H(d, a, b0, b1) \
    asm volatile("mma.sync.aligned.m16n8k16.row.col.f32.f16.f16.f32 " \
        "{%0,%1,%2,%3}, {%4,%5,%6,%7}, {%8,%9}, {%0,%1,%2,%3};" \
        : "+f"((d)[0]), "+f"((d)[1]), "+f"((d)[2]), "+f"((d)[3]) \
        : "r"((a)[0]), "r"((a)[1]), "r"((a)[2]), "r"((a)[3]), "r"(b0), "r"(b1))

__device__ __forceinline__ void split_f16(float v, __half& h, __half& l) {
    h = __float2half_rn(v);
    l = __float2half_rn(v - __half2float(h));
}

// ---------------- stage 0a ---------------------------------------------------
__global__ void prep_lam_kernel(const float* __restrict__ Lre,
                                const float* __restrict__ Lim,
                                const float* __restrict__ log_step)
{
    int p = threadIdx.x;
    if (p >= PD) return;
    float lr = Lre[p], li = Lim[p];
    float step = (float)exp((double)log_step[p]);
    double theta = (double)(li * step);
    double a     = (double)(lr * step);
    double s, c;
    sincos(theta, &s, &c);
    double mag = exp(a);
    float lbr = (float)(mag * c);
    float lbi = (float)(mag * s);
    g_lam[p] = make_float2(lbr, lbi);
    double s64, c64;
    sincos(64.0 * theta, &s64, &c64);
    double mag64 = exp(64.0 * a);
    g_lam64[p] = make_float2((float)(mag64 * c64), (float)(mag64 * s64));
    float ar = lbr - 1.0f, ai = lbi;
    float den = lr*lr + li*li;
    g_f[p] = make_float2((ar*lr + ai*li) / den, (ai*lr - ar*li) / den);
}

// ---------------- stage 0b ---------------------------------------------------
// W1: [np][h] scaled by 1024 (keeps fp16 hi AND lo in normal/usable range)
// W2: [h][np]
__global__ void prep_w_kernel(const float* __restrict__ Bv,   // (P,H,2)
                              const float* __restrict__ Cv)   // (H,P,2)
{
    int t = blockIdx.x * blockDim.x + threadIdx.x;
    {
        int n = t >> 10, h = t & 1023;
        int p = n >> 1, c = n & 1;
        float2 f = g_f[p];
        float br = Bv[((size_t)p*HD + h)*2 + 0];
        float bi = Bv[((size_t)p*HD + h)*2 + 1];
        float w = (c == 0) ? (f.x*br - f.y*bi) : (f.x*bi + f.y*br);
        split_f16(w * W1SC, g_W1h[t], g_W1l[t]);
    }
    {
        // t = h*1024 + 2p + c -> g_W2h[h][np]
        float w = Cv[t] * ((t & 1) ? -2.0f : 2.0f);
        split_f16(w, g_W2h[t], g_W2l[t]);
    }
}

__global__ void conv_sig_kernel(const float* __restrict__ sig)
{
    size_t t = (size_t)blockIdx.x * blockDim.x + threadIdx.x;
    float4 v = *(const float4*)(sig + t*4);
    __half2 a0, a1;
    a0 = __halves2half2(__float2half_rn(v.x), __float2half_rn(v.y));
    a1 = __halves2half2(__float2half_rn(v.z), __float2half_rn(v.w));
    ((__half2*)g_Af)[t*2+0] = a0;
    ((__half2*)g_Af)[t*2+1] = a1;
}

// ---------------- HMMA GEMM: fp16 2-pass (A single, W hi/lo) -----------------
#define AS_STRIDE 40
#define TILE_SM   (128*AS_STRIDE*2)    // 10240 B
#define BUF_SM    (3*TILE_SM)          // A, Wh, Wl = 30720 B per stage
#define NSTAGE    4
#define GEMM_SMEM (NSTAGE*BUF_SM)      // 122880 B

template<bool SECOND>
__global__ __launch_bounds__(512, 1)
void gemm_hmma(float* __restrict__ Cout, const float* __restrict__ sig,
               const float* __restrict__ Dv)
{
    extern __shared__ __align__(16) char smem[];
    const uint32_t sb = smem_u32(smem);
    const int tid = threadIdx.x;
    const int wid = tid >> 5, lane = tid & 31;
    const int wm = wid & 3, wn = wid >> 2;           // 4x4 warps, 32x32 tiles
    const int bm = blockIdx.y * 128, bn = blockIdx.x * 128;

    const __half* srcs[3];
    if (SECOND) { srcs[0] = g_Xf; srcs[1] = g_W2h; srcs[2] = g_W2l; }
    else        { srcs[0] = g_Af; srcs[1] = g_W1h; srcs[2] = g_W1l; }

    const int ldrow = tid >> 2;
    const int ldc   = tid & 3;

    auto issue = [&](int buf, int k0) {
        #pragma unroll
        for (int t3 = 0; t3 < 3; t3++) {
            const __half* src = srcs[t3];
            const int rowbase = (t3 == 0) ? bm : bn;
            const void* g = src + (size_t)(rowbase + ldrow) * 1024 + k0 + ldc * 8;
            uint32_t d = sb + buf*BUF_SM + t3*TILE_SM + ldrow*(AS_STRIDE*2) + ldc*16;
            cpa16(d, g);
        }
        CP_COMMIT();
    };

    float acc[2][4][4];
    #pragma unroll
    for (int i = 0; i < 2; i++)
        #pragma unroll
        for (int j = 0; j < 4; j++)
            #pragma unroll
            for (int q = 0; q < 4; q++) acc[i][j][q] = 0.0f;

    const int a_row = wm*32 + (lane & 15);
    const int a_kc8 = (lane >> 4) << 3;
    const int b_row = wn*32 + ((lane >> 4) << 3) + (lane & 7);
    const int b_kc8 = ((lane >> 3) & 1) << 3;

    issue(0, 0);
    issue(1, 32);
    issue(2, 64);

    for (int k = 0; k < 32; k++) {
        if (k < 30)       asm volatile("cp.async.wait_group 2;" ::: "memory");
        else if (k == 30) asm volatile("cp.async.wait_group 1;" ::: "memory");
        else              asm volatile("cp.async.wait_group 0;" ::: "memory");
        __syncthreads();

        if (k < 29) issue((k + 3) & (NSTAGE - 1), (k + 3) * 32);

        const uint32_t base = sb + (k & (NSTAGE - 1)) * BUF_SM;
        #pragma unroll
        for (int ks = 0; ks < 2; ks++) {
            const int k16 = ks * 16;
            uint32_t ah[2][4], b[2][4];
            #pragma unroll
            for (int mf = 0; mf < 2; mf++) {
                uint32_t ao = base + (uint32_t)((a_row + mf*16)*(AS_STRIDE*2) + (k16 + a_kc8)*2);
                LDSM_X4(ah[mf][0], ah[mf][1], ah[mf][2], ah[mf][3], ao);
            }
            // Wh pass
            #pragma unroll
            for (int nf2 = 0; nf2 < 2; nf2++) {
                uint32_t bo = base + 1*TILE_SM +
                    (uint32_t)((b_row + nf2*16)*(AS_STRIDE*2) + (k16 + b_kc8)*2);
                LDSM_X4(b[nf2][0], b[nf2][1], b[nf2][2], b[nf2][3], bo);
            }
            #pragma unroll
            for (int mf = 0; mf < 2; mf++)
                #pragma unroll
                for (int nf = 0; nf < 4; nf++) {
                    const int n2 = nf >> 1, hh = (nf & 1) << 1;
                    MMA16816H(acc[mf][nf], ah[mf], b[n2][hh], b[n2][hh+1]);
                }
            // Wl pass
            #pragma unroll
            for (int nf2 = 0; nf2 < 2; nf2++) {
                uint32_t bo = base + 2*TILE_SM +
                    (uint32_t)((b_row + nf2*16)*(AS_STRIDE*2) + (k16 + b_kc8)*2);
                LDSM_X4(b[nf2][0], b[nf2][1], b[nf2][2], b[nf2][3], bo);
            }
            #pragma unroll
            for (int mf = 0; mf < 2; mf++)
                #pragma unroll
                for (int nf = 0; nf < 4; nf++) {
                    const int n2 = nf >> 1, hh = (nf & 1) << 1;
                    MMA16816H(acc[mf][nf], ah[mf], b[n2][hh], b[n2][hh+1]);
                }
        }
    }

    // ---- epilogue ----
    const int r0 = lane >> 2;
    const int c0 = (lane & 3) * 2;
    #pragma unroll
    for (int mf = 0; mf < 2; mf++) {
        #pragma unroll
        for (int nf = 0; nf < 4; nf++) {
            int row = bm + wm*32 + mf*16 + r0;
            int col = bn + wn*32 + nf*8 + c0;
            float2 v0 = make_float2(acc[mf][nf][0], acc[mf][nf][1]);
            float2 v1 = make_float2(acc[mf][nf][2], acc[mf][nf][3]);
            size_t o0 = (size_t)row * 1024 + col;
            size_t o1 = (size_t)(row + 8) * 1024 + col;
            if (SECOND) {
                float2 s0 = *(const float2*)(sig + o0);
                float2 s1 = *(const float2*)(sig + o1);
                float2 d2 = *(const float2*)(Dv + col);
                v0.x = fmaf(d2.x, s0.x, v0.x); v0.y = fmaf(d2.y, s0.y, v0.y);
                v1.x = fmaf(d2.x, s1.x, v1.x); v1.y = fmaf(d2.y, s1.y, v1.y);
            }
            float* out = SECOND ? Cout : g_X;
            *(float2*)(out + o0) = v0;
            *(float2*)(out + o1) = v1;
        }
    }
}

// ---------------- chunked scan (g_X holds 1024*Bu; divide on load) -----------
__global__ void scanA_kernel()
{
    int id = blockIdx.x * blockDim.x + threadIdx.x;
    int p = id & (PD - 1);
    int bc = id >> 9;
    int c = bc & (CH - 1);
    int b = bc >> 5;
    float2 lam = g_lam[p];
    const float2* base = (const float2*)(g_X + (size_t)(b*LSEQ + c*LC) * NN) + p;
    float xr = 0.0f, xi = 0.0f;
    #pragma unroll 4
    for (int j = 0; j < LC; j++) {
        float2 bu = base[(size_t)j * (NN/2)];
        bu.x *= INVSC; bu.y *= INVSC;
        float nr = fmaf(lam.x, xr, fmaf(-lam.y, xi, bu.x));
        float ni = fmaf(lam.x, xi, fmaf( lam.y, xr, bu.y));
        xr = nr; xi = ni;
    }
    g_carry[id] = make_float2(xr, xi);
}

__global__ void scanB_kernel()
{
    int id = blockIdx.x * blockDim.x + threadIdx.x;
    if (id >= BATCH * PD) return;
    int b = id >> 9, p = id & (PD - 1);
    float2 l64 = g_lam64[p];
    float2 cur = make_float2(0.0f, 0.0f);
    for (int c = 0; c < CH; c++) {
        int idx = (b*CH + c)*PD + p;
        g_cin[idx] = cur;
        float2 bc = g_carry[idx];
        float nr = fmaf(l64.x, cur.x, fmaf(-l64.y, cur.y, bc.x));
        float ni = fmaf(l64.x, cur.y, fmaf( l64.y, cur.x, bc.y));
        cur = make_float2(nr, ni);
    }
}

__global__ void scanC_kernel(float* __restrict__ state_out, int mode)
{
    int id = blockIdx.x * blockDim.x + threadIdx.x;
    int p = id & (PD - 1);
    int bc = id >> 9;
    int c = bc & (CH - 1);
    int b = bc >> 5;
    float2 lam = g_lam[p];
    float2 x = g_cin[id];
    size_t row0 = (size_t)(b*LSEQ + c*LC);
    const float2* base = (const float2*)(g_X + row0 * NN) + p;
    __half2* oxf = (__half2*)g_Xf + row0 * (NN/2) + p;
    #pragma unroll 4
    for (int j = 0; j < LC; j++) {
        float2 bu = base[(size_t)j * (NN/2)];
        bu.x *= INVSC; bu.y *= INVSC;
        float nr = fmaf(lam.x, x.x, fmaf(-lam.y, x.y, bu.x));
        float ni = fmaf(lam.x, x.y, fmaf( lam.y, x.x, bu.y));
        x = make_float2(nr, ni);
        oxf[(size_t)j * (NN/2)] = __halves2half2(__float2half_rn(x.x), __float2half_rn(x.y));
    }
    if (c == CH - 1) {
        int sid = b * PD + p;
        if (mode == 2)       ((float2*)state_out)[sid] = x;
        else if (mode == 1)  state_out[sid] = x.x;
    }
}

// ---------------- launch -----------------------------------------------------
extern "C" void kernel_launch(void* const* d_in, const int* in_sizes, int n_in,
                              void* d_out, int out_size)
{
    const float* signal = (const float*)d_in[0];
    const float* Lre    = (const float*)d_in[2];
    const float* Lim    = (const float*)d_in[3];
    const float* Bv     = (const float*)d_in[4];
    const float* Cv     = (const float*)d_in[5];
    const float* Dv     = (const float*)d_in[6];
    const float* lstep  = (const float*)d_in[7];
    (void)in_sizes; (void)n_in;

    float* y = (float*)d_out;
    long rem = (long)out_size - (long)M * HD;
    int mode = (rem >= 2L*BATCH*PD) ? 2 : (rem >= (long)BATCH*PD ? 1 : 0);
    float* state_out = y + (size_t)M * HD;

    cudaFuncSetAttribute(gemm_hmma<false>, cudaFuncAttributeMaxDynamicSharedMemorySize, GEMM_SMEM);
    cudaFuncSetAttribute(gemm_hmma<true>,  cudaFuncAttributeMaxDynamicSharedMemorySize, GEMM_SMEM);

    prep_lam_kernel<<<1, PD>>>(Lre, Lim, lstep);
    prep_w_kernel<<<(NN*KK)/256, 256>>>(Bv, Cv);
    conv_sig_kernel<<<((size_t)M*KK/4)/256, 256>>>(signal);

    dim3 grid(NN/128, M/128);   // (8, 128)
    gemm_hmma<false><<<grid, 512, GEMM_SMEM>>>(nullptr, nullptr, nullptr);

    scanA_kernel<<<(BATCH*CH*PD)/256, 256>>>();
    scanB_kernel<<<(BATCH*PD)/256, 256>>>();
    scanC_kernel<<<(BATCH*CH*PD)/256, 256>>>(state_out, mode);

    gemm_hmma<true><<<grid, 512, GEMM_SMEM>>>(y, signal, Dv);
}

// round 12
// speedup vs baseline: 2.2941x; 1.7694x over previous
#include <cuda_runtime.h>
#include <cuda_bf16.h>
#include <cuda_fp16.h>
#include <cstdint>
#include <math.h>

#define BATCH 8
#define LSEQ  2048
#define HD    1024
#define PD    512
#define M     (BATCH*LSEQ)   // 16384
#define NN    1024           // 2*P
#define KK    1024
#define CH    32
#define LC    64
#define W1SC  1024.0f        // W1 pre-scale (exact power of 2)
#define INVSC (1.0f/1024.0f)

// ---------------- scratch ---------------------------------------------------
__device__ float   g_X  [(size_t)M*NN];    // 1024*Bu fp32 (GEMM1 out, scan in)
__device__ __half  g_Af [(size_t)M*KK];    // signal fp16
__device__ __half  g_Xf [(size_t)M*NN];    // xs fp16
__device__ __half  g_W1f[(size_t)NN*KK];   // [np][h], scaled by 1024
__device__ __half  g_W2f[(size_t)NN*KK];   // [h][np]
__device__ float2 g_lam[PD];
__device__ float2 g_lam64[PD];
__device__ float2 g_f[PD];
__device__ float2 g_carry[BATCH*CH*PD];
__device__ float2 g_cin  [BATCH*CH*PD];

// ---------------- helpers ----------------------------------------------------
__device__ __forceinline__ uint32_t smem_u32(const void* p) {
    uint32_t a;
    asm("{ .reg .u64 t; cvta.to.shared.u64 t, %1; cvt.u32.u64 %0, t; }" : "=r"(a) : "l"(p));
    return a;
}
__device__ __forceinline__ void cpa16(uint32_t dst, const void* src) {
    asm volatile("cp.async.cg.shared.global [%0], [%1], 16;" :: "r"(dst), "l"(src));
}
#define CP_COMMIT() asm volatile("cp.async.commit_group;" ::: "memory")
#define LDSM_X4(r0,r1,r2,r3,addr) \
    asm volatile("ldmatrix.sync.aligned.m8n8.x4.shared.b16 {%0,%1,%2,%3}, [%4];" \
        : "=r"(r0), "=r"(r1), "=r"(r2), "=r"(r3) : "r"(addr))
#define MMA16816H(d, a, b0, b1) \
    asm volatile("mma.sync.aligned.m16n8k16.row.col.f32.f16.f16.f32 " \
        "{%0,%1,%2,%3}, {%4,%5,%6,%7}, {%8,%9}, {%0,%1,%2,%3};" \
        : "+f"((d)[0]), "+f"((d)[1]), "+f"((d)[2]), "+f"((d)[3]) \
        : "r"((a)[0]), "r"((a)[1]), "r"((a)[2]), "r"((a)[3]), "r"(b0), "r"(b1))

// ---------------- stage 0a ---------------------------------------------------
__global__ void prep_lam_kernel(const float* __restrict__ Lre,
                                const float* __restrict__ Lim,
                                const float* __restrict__ log_step)
{
    int p = threadIdx.x;
    if (p >= PD) return;
    float lr = Lre[p], li = Lim[p];
    float step = (float)exp((double)log_step[p]);
    double theta = (double)(li * step);
    double a     = (double)(lr * step);
    double s, c;
    sincos(theta, &s, &c);
    double mag = exp(a);
    float lbr = (float)(mag * c);
    float lbi = (float)(mag * s);
    g_lam[p] = make_float2(lbr, lbi);
    double s64, c64;
    sincos(64.0 * theta, &s64, &c64);
    double mag64 = exp(64.0 * a);
    g_lam64[p] = make_float2((float)(mag64 * c64), (float)(mag64 * s64));
    float ar = lbr - 1.0f, ai = lbi;
    float den = lr*lr + li*li;
    g_f[p] = make_float2((ar*lr + ai*li) / den, (ai*lr - ar*li) / den);
}

// ---------------- stage 0b ---------------------------------------------------
__global__ void prep_w_kernel(const float* __restrict__ Bv,   // (P,H,2)
                              const float* __restrict__ Cv)   // (H,P,2)
{
    int t = blockIdx.x * blockDim.x + threadIdx.x;
    {
        int n = t >> 10, h = t & 1023;
        int p = n >> 1, c = n & 1;
        float2 f = g_f[p];
        float br = Bv[((size_t)p*HD + h)*2 + 0];
        float bi = Bv[((size_t)p*HD + h)*2 + 1];
        float w = (c == 0) ? (f.x*br - f.y*bi) : (f.x*bi + f.y*br);
        g_W1f[t] = __float2half_rn(w * W1SC);
    }
    {
        // t = h*1024 + 2p + c -> g_W2f[h][np]
        float w = Cv[t] * ((t & 1) ? -2.0f : 2.0f);
        g_W2f[t] = __float2half_rn(w);
    }
}

__global__ void conv_sig_kernel(const float* __restrict__ sig)
{
    size_t t = (size_t)blockIdx.x * blockDim.x + threadIdx.x;
    float4 v = *(const float4*)(sig + t*4);
    ((__half2*)g_Af)[t*2+0] = __halves2half2(__float2half_rn(v.x), __float2half_rn(v.y));
    ((__half2*)g_Af)[t*2+1] = __halves2half2(__float2half_rn(v.z), __float2half_rn(v.w));
}

// ---------------- HMMA GEMM: single fp16, 1 pass -----------------------------
#define AS_STRIDE 40
#define TILE_SM   (128*AS_STRIDE*2)    // 10240 B
#define BUF_SM    (2*TILE_SM)          // A, W = 20480 B per stage
#define NSTAGE    4
#define GEMM_SMEM (NSTAGE*BUF_SM)      // 81920 B

template<bool SECOND>
__global__ __launch_bounds__(512, 1)
void gemm_hmma(float* __restrict__ Cout, const float* __restrict__ sig,
               const float* __restrict__ Dv)
{
    extern __shared__ __align__(16) char smem[];
    const uint32_t sb = smem_u32(smem);
    const int tid = threadIdx.x;
    const int wid = tid >> 5, lane = tid & 31;
    const int wm = wid & 3, wn = wid >> 2;           // 4x4 warps, 32x32 tiles
    const int bm = blockIdx.y * 128, bn = blockIdx.x * 128;

    const __half* srcA = SECOND ? g_Xf  : g_Af;
    const __half* srcW = SECOND ? g_W2f : g_W1f;

    const int ldrow = tid >> 2;
    const int ldc   = tid & 3;

    auto issue = [&](int buf, int k0) {
        {
            const void* g = srcA + (size_t)(bm + ldrow) * 1024 + k0 + ldc * 8;
            uint32_t d = sb + buf*BUF_SM + ldrow*(AS_STRIDE*2) + ldc*16;
            cpa16(d, g);
        }
        {
            const void* g = srcW + (size_t)(bn + ldrow) * 1024 + k0 + ldc * 8;
            uint32_t d = sb + buf*BUF_SM + TILE_SM + ldrow*(AS_STRIDE*2) + ldc*16;
            cpa16(d, g);
        }
        CP_COMMIT();
    };

    float acc[2][4][4];
    #pragma unroll
    for (int i = 0; i < 2; i++)
        #pragma unroll
        for (int j = 0; j < 4; j++)
            #pragma unroll
            for (int q = 0; q < 4; q++) acc[i][j][q] = 0.0f;

    const int a_row = wm*32 + (lane & 15);
    const int a_kc8 = (lane >> 4) << 3;
    const int b_row = wn*32 + ((lane >> 4) << 3) + (lane & 7);
    const int b_kc8 = ((lane >> 3) & 1) << 3;

    issue(0, 0);
    issue(1, 32);
    issue(2, 64);

    for (int k = 0; k < 32; k++) {
        if (k < 30)       asm volatile("cp.async.wait_group 2;" ::: "memory");
        else if (k == 30) asm volatile("cp.async.wait_group 1;" ::: "memory");
        else              asm volatile("cp.async.wait_group 0;" ::: "memory");
        __syncthreads();

        if (k < 29) issue((k + 3) & (NSTAGE - 1), (k + 3) * 32);

        const uint32_t base = sb + (k & (NSTAGE - 1)) * BUF_SM;
        #pragma unroll
        for (int ks = 0; ks < 2; ks++) {
            const int k16 = ks * 16;
            uint32_t ah[2][4], b[2][4];
            #pragma unroll
            for (int mf = 0; mf < 2; mf++) {
                uint32_t ao = base + (uint32_t)((a_row + mf*16)*(AS_STRIDE*2) + (k16 + a_kc8)*2);
                LDSM_X4(ah[mf][0], ah[mf][1], ah[mf][2], ah[mf][3], ao);
            }
            #pragma unroll
            for (int nf2 = 0; nf2 < 2; nf2++) {
                uint32_t bo = base + TILE_SM +
                    (uint32_t)((b_row + nf2*16)*(AS_STRIDE*2) + (k16 + b_kc8)*2);
                LDSM_X4(b[nf2][0], b[nf2][1], b[nf2][2], b[nf2][3], bo);
            }
            #pragma unroll
            for (int mf = 0; mf < 2; mf++)
                #pragma unroll
                for (int nf = 0; nf < 4; nf++) {
                    const int n2 = nf >> 1, hh = (nf & 1) << 1;
                    MMA16816H(acc[mf][nf], ah[mf], b[n2][hh], b[n2][hh+1]);
                }
        }
    }

    // ---- epilogue ----
    const int r0 = lane >> 2;
    const int c0 = (lane & 3) * 2;
    #pragma unroll
    for (int mf = 0; mf < 2; mf++) {
        #pragma unroll
        for (int nf = 0; nf < 4; nf++) {
            int row = bm + wm*32 + mf*16 + r0;
            int col = bn + wn*32 + nf*8 + c0;
            float2 v0 = make_float2(acc[mf][nf][0], acc[mf][nf][1]);
            float2 v1 = make_float2(acc[mf][nf][2], acc[mf][nf][3]);
            size_t o0 = (size_t)row * 1024 + col;
            size_t o1 = (size_t)(row + 8) * 1024 + col;
            if (SECOND) {
                float2 s0 = *(const float2*)(sig + o0);
                float2 s1 = *(const float2*)(sig + o1);
                float2 d2 = *(const float2*)(Dv + col);
                v0.x = fmaf(d2.x, s0.x, v0.x); v0.y = fmaf(d2.y, s0.y, v0.y);
                v1.x = fmaf(d2.x, s1.x, v1.x); v1.y = fmaf(d2.y, s1.y, v1.y);
            }
            float* out = SECOND ? Cout : g_X;
            *(float2*)(out + o0) = v0;
            *(float2*)(out + o1) = v1;
        }
    }
}

// ---------------- chunked scan (g_X holds 1024*Bu; divide on load) -----------
__global__ void scanA_kernel()
{
    int id = blockIdx.x * blockDim.x + threadIdx.x;
    int p = id & (PD - 1);
    int bc = id >> 9;
    int c = bc & (CH - 1);
    int b = bc >> 5;
    float2 lam = g_lam[p];
    const float2* base = (const float2*)(g_X + (size_t)(b*LSEQ + c*LC) * NN) + p;
    float xr = 0.0f, xi = 0.0f;
    #pragma unroll 4
    for (int j = 0; j < LC; j++) {
        float2 bu = base[(size_t)j * (NN/2)];
        bu.x *= INVSC; bu.y *= INVSC;
        float nr = fmaf(lam.x, xr, fmaf(-lam.y, xi, bu.x));
        float ni = fmaf(lam.x, xi, fmaf( lam.y, xr, bu.y));
        xr = nr; xi = ni;
    }
    g_carry[id] = make_float2(xr, xi);
}

__global__ void scanB_kernel()
{
    int id = blockIdx.x * blockDim.x + threadIdx.x;
    if (id >= BATCH * PD) return;
    int b = id >> 9, p = id & (PD - 1);
    float2 l64 = g_lam64[p];
    float2 cur = make_float2(0.0f, 0.0f);
    for (int c = 0; c < CH; c++) {
        int idx = (b*CH + c)*PD + p;
        g_cin[idx] = cur;
        float2 bc = g_carry[idx];
        float nr = fmaf(l64.x, cur.x, fmaf(-l64.y, cur.y, bc.x));
        float ni = fmaf(l64.x, cur.y, fmaf( l64.y, cur.x, bc.y));
        cur = make_float2(nr, ni);
    }
}

__global__ void scanC_kernel(float* __restrict__ state_out, int mode)
{
    int id = blockIdx.x * blockDim.x + threadIdx.x;
    int p = id & (PD - 1);
    int bc = id >> 9;
    int c = bc & (CH - 1);
    int b = bc >> 5;
    float2 lam = g_lam[p];
    float2 x = g_cin[id];
    size_t row0 = (size_t)(b*LSEQ + c*LC);
    const float2* base = (const float2*)(g_X + row0 * NN) + p;
    __half2* oxf = (__half2*)g_Xf + row0 * (NN/2) + p;
    #pragma unroll 4
    for (int j = 0; j < LC; j++) {
        float2 bu = base[(size_t)j * (NN/2)];
        bu.x *= INVSC; bu.y *= INVSC;
        float nr = fmaf(lam.x, x.x, fmaf(-lam.y, x.y, bu.x));
        float ni = fmaf(lam.x, x.y, fmaf( lam.y, x.x, bu.y));
        x = make_float2(nr, ni);
        oxf[(size_t)j * (NN/2)] = __halves2half2(__float2half_rn(x.x), __float2half_rn(x.y));
    }
    if (c == CH - 1) {
        int sid = b * PD + p;
        if (mode == 2)       ((float2*)state_out)[sid] = x;
        else if (mode == 1)  state_out[sid] = x.x;
    }
}

// ---------------- launch -----------------------------------------------------
extern "C" void kernel_launch(void* const* d_in, const int* in_sizes, int n_in,
                              void* d_out, int out_size)
{
    const float* signal = (const float*)d_in[0];
    const float* Lre    = (const float*)d_in[2];
    const float* Lim    = (const float*)d_in[3];
    const float* Bv     = (const float*)d_in[4];
    const float* Cv     = (const float*)d_in[5];
    const float* Dv     = (const float*)d_in[6];
    const float* lstep  = (const float*)d_in[7];
    (void)in_sizes; (void)n_in;

    float* y = (float*)d_out;
    long rem = (long)out_size - (long)M * HD;
    int mode = (rem >= 2L*BATCH*PD) ? 2 : (rem >= (long)BATCH*PD ? 1 : 0);
    float* state_out = y + (size_t)M * HD;

    cudaFuncSetAttribute(gemm_hmma<false>, cudaFuncAttributeMaxDynamicSharedMemorySize, GEMM_SMEM);
    cudaFuncSetAttribute(gemm_hmma<true>,  cudaFuncAttributeMaxDynamicSharedMemorySize, GEMM_SMEM);

    prep_lam_kernel<<<1, PD>>>(Lre, Lim, lstep);
    prep_w_kernel<<<(NN*KK)/256, 256>>>(Bv, Cv);
    conv_sig_kernel<<<((size_t)M*KK/4)/256, 256>>>(signal);

    dim3 grid(NN/128, M/128);   // (8, 128)
    gemm_hmma<false><<<grid, 512, GEMM_SMEM>>>(nullptr, nullptr, nullptr);

    scanA_kernel<<<(BATCH*CH*PD)/256, 256>>>();
    scanB_kernel<<<(BATCH*PD)/256, 256>>>();
    scanC_kernel<<<(BATCH*CH*PD)/256, 256>>>(state_out, mode);

    gemm_hmma<true><<<grid, 512, GEMM_SMEM>>>(y, signal, Dv);
}